// round 1
// baseline (speedup 1.0000x reference)
#include <cuda_runtime.h>
#include <math.h>

#define NQ 12
#define DIM 4096          // 2^12 amplitudes
#define NLAYERS 3
#define SIM_THREADS 1024
#define AMPS_PER_THREAD (DIM / SIM_THREADS)   // 4

__device__ float g_pix[16];   // result of circuit + MLP (16 sigmoid pixels)

__device__ __forceinline__ float2 cmul(float2 a, float2 b) {
    return make_float2(a.x * b.x - a.y * b.y, a.x * b.y + a.y * b.x);
}
__device__ __forceinline__ float2 cadd(float2 a, float2 b) {
    return make_float2(a.x + b.x, a.y + b.y);
}

// One CTA simulates the whole 12-qubit circuit in shared memory, then runs
// the tiny MLP head and writes 16 floats to g_pix.
__global__ __launch_bounds__(SIM_THREADS, 1)
void qae_sim_kernel(const float* __restrict__ w,     // (3,12,3)
                    const float* __restrict__ W1,    // (32,12)
                    const float* __restrict__ b1,    // (32,)
                    const float* __restrict__ W2,    // (16,32)
                    const float* __restrict__ b2)    // (16,)
{
    __shared__ float2 sA[DIM];           // 32 KB statevector
    __shared__ float2 sM[NLAYERS * NQ][4]; // fused RZ@RY@RX per (layer,qubit)
    __shared__ float  sPart[32][12];     // per-warp partial <Z_q>
    __shared__ float  sZ[12];
    __shared__ float  sH[32];

    const int tid = threadIdx.x;

    // --- init |0...0> ---
    #pragma unroll
    for (int k = 0; k < AMPS_PER_THREAD; k++)
        sA[tid + k * SIM_THREADS] = make_float2(0.f, 0.f);
    if (tid == 0) sA[0] = make_float2(1.f, 0.f);

    // --- precompute all 36 single-qubit gate matrices in parallel ---
    if (tid < NLAYERS * NQ) {
        const float* wp = w + tid * 3;   // contiguous (l,q,3) layout
        float hx = 0.5f * wp[0], hy = 0.5f * wp[1], hz = 0.5f * wp[2];
        float cx, sx, cy, sy, cz, sz;
        sincosf(hx, &sx, &cx);
        sincosf(hy, &sy, &cy);
        sincosf(hz, &sz, &cz);
        float2 RX00 = make_float2(cx, 0.f), RX01 = make_float2(0.f, -sx);
        float2 RX10 = make_float2(0.f, -sx), RX11 = make_float2(cx, 0.f);
        float2 RY00 = make_float2(cy, 0.f), RY01 = make_float2(-sy, 0.f);
        float2 RY10 = make_float2(sy, 0.f), RY11 = make_float2(cy, 0.f);
        float2 RZ0 = make_float2(cz, -sz), RZ1 = make_float2(cz, sz);
        // A = RY @ RX
        float2 A00 = cadd(cmul(RY00, RX00), cmul(RY01, RX10));
        float2 A01 = cadd(cmul(RY00, RX01), cmul(RY01, RX11));
        float2 A10 = cadd(cmul(RY10, RX00), cmul(RY11, RX10));
        float2 A11 = cadd(cmul(RY10, RX01), cmul(RY11, RX11));
        // M = RZ @ A
        sM[tid][0] = cmul(RZ0, A00);
        sM[tid][1] = cmul(RZ0, A01);
        sM[tid][2] = cmul(RZ1, A10);
        sM[tid][3] = cmul(RZ1, A11);
    }
    __syncthreads();

    // --- circuit ---
    for (int l = 0; l < NLAYERS; l++) {
        // 12 single-qubit gates (they commute; one barrier each for safety)
        for (int q = 0; q < NQ; q++) {
            const int p = 11 - q;          // JAX row-major: qubit q <-> bit 11-q
            const int m = 1 << p;
            float2 M00 = sM[l * NQ + q][0];
            float2 M01 = sM[l * NQ + q][1];
            float2 M10 = sM[l * NQ + q][2];
            float2 M11 = sM[l * NQ + q][3];
            #pragma unroll
            for (int k = 0; k < DIM / 2 / SIM_THREADS; k++) {   // 2 pairs/thread
                int pr = tid + k * SIM_THREADS;
                int i0 = ((pr >> p) << (p + 1)) | (pr & (m - 1));
                int i1 = i0 | m;
                float2 a0 = sA[i0], a1 = sA[i1];
                sA[i0] = cadd(cmul(M00, a0), cmul(M01, a1));
                sA[i1] = cadd(cmul(M10, a0), cmul(M11, a1));
            }
            __syncthreads();
        }
        // CNOT ring: compose all 12 CNOTs into one basis-state permutation.
        // new[i] = old[g_0(g_1(...g_11(i)))] with g_q: flip bit t if bit c set.
        float2 v[AMPS_PER_THREAD];
        #pragma unroll
        for (int k = 0; k < AMPS_PER_THREAD; k++) {
            int i = tid + k * SIM_THREADS;
            int j = i;
            #pragma unroll
            for (int q = NQ - 1; q >= 0; q--) {
                int c = 11 - q;
                int t = 11 - ((q + 1) % NQ);
                if ((j >> c) & 1) j ^= (1 << t);
            }
            v[k] = sA[j];
        }
        __syncthreads();
        #pragma unroll
        for (int k = 0; k < AMPS_PER_THREAD; k++)
            sA[tid + k * SIM_THREADS] = v[k];
        __syncthreads();
    }

    // --- deterministic <Z_q> reduction ---
    float zloc[12];
    #pragma unroll
    for (int q = 0; q < 12; q++) zloc[q] = 0.f;
    #pragma unroll
    for (int k = 0; k < AMPS_PER_THREAD; k++) {
        int i = tid + k * SIM_THREADS;
        float2 a = sA[i];
        float pr = a.x * a.x + a.y * a.y;
        #pragma unroll
        for (int q = 0; q < 12; q++) {
            // qubit q <-> bit 11-q
            zloc[q] += ((i >> (11 - q)) & 1) ? -pr : pr;
        }
    }
    #pragma unroll
    for (int q = 0; q < 12; q++) {
        float x = zloc[q];
        #pragma unroll
        for (int off = 16; off > 0; off >>= 1)
            x += __shfl_down_sync(0xFFFFFFFFu, x, off);
        zloc[q] = x;
    }
    int warp = tid >> 5, lane = tid & 31;
    if (lane == 0) {
        #pragma unroll
        for (int q = 0; q < 12; q++) sPart[warp][q] = zloc[q];
    }
    __syncthreads();
    if (tid < 12) {
        float s = 0.f;
        #pragma unroll
        for (int wi = 0; wi < 32; wi++) s += sPart[wi][tid];
        sZ[tid] = s;
    }
    __syncthreads();

    // --- MLP head: 12 -> 32 (ReLU) -> 16 (sigmoid) ---
    if (tid < 32) {
        float acc = b1[tid];
        #pragma unroll
        for (int k = 0; k < 12; k++) acc += W1[tid * 12 + k] * sZ[k];
        sH[tid] = fmaxf(acc, 0.f);
    }
    __syncthreads();
    if (tid < 16) {
        float acc = b2[tid];
        #pragma unroll
        for (int k = 0; k < 32; k++) acc += W2[tid * 32 + k] * sH[k];
        g_pix[tid] = 1.f / (1.f + expf(-acc));
    }
}

// Broadcast the 16-float pattern across the whole 64 MiB output.
__global__ __launch_bounds__(256)
void qae_bcast_kernel(float4* __restrict__ out, int n4)
{
    __shared__ float4 sp[4];
    if (threadIdx.x < 4)
        sp[threadIdx.x] = reinterpret_cast<const float4*>(g_pix)[threadIdx.x];
    __syncthreads();

    int idx = blockIdx.x * blockDim.x + threadIdx.x;
    int stride = gridDim.x * blockDim.x;           // multiple of 4
    if (idx >= n4) return;
    float4 v = sp[idx & 3];                        // constant per thread
    for (; idx < n4; idx += stride)
        out[idx] = v;
}

extern "C" void kernel_launch(void* const* d_in, const int* in_sizes, int n_in,
                              void* d_out, int out_size)
{
    // metadata order: images, qweights, W1, b1, W2, b2
    const float* w  = (const float*)d_in[1];
    const float* W1 = (const float*)d_in[2];
    const float* b1 = (const float*)d_in[3];
    const float* W2 = (const float*)d_in[4];
    const float* b2 = (const float*)d_in[5];

    qae_sim_kernel<<<1, SIM_THREADS>>>(w, W1, b1, W2, b2);

    int n4 = out_size / 4;                          // out_size = B*16 floats
    int threads = 256;
    int blocks = 2048;                              // grid-stride, ~8 f4/thread
    int needed = (n4 + threads - 1) / threads;
    if (blocks > needed) blocks = needed;
    qae_bcast_kernel<<<blocks, threads>>>((float4*)d_out, n4);
}

// round 2
// speedup vs baseline: 1.1220x; 1.1220x over previous
#include <cuda_runtime.h>
#include <math.h>

#define SIM_THREADS 1024

__device__ float g_pix[16];   // 16 sigmoid pixels (final pattern)

__device__ __forceinline__ float2 cmul(float2 a, float2 b) {
    return make_float2(a.x * b.x - a.y * b.y, a.x * b.y + a.y * b.x);
}
__device__ __forceinline__ float2 cmac(float2 m, float2 a, float2 acc) {
    acc.x = fmaf(m.x, a.x, fmaf(-m.y, a.y, acc.x));
    acc.y = fmaf(m.x, a.y, fmaf(m.y, a.x, acc.y));
    return acc;
}

// In-place 2-bit (4x4) gate stage on bits (B, B+1). Each thread owns one quad
// -> no cross-thread hazard; one barrier between stages.
template<int B>
__device__ __forceinline__ void apply_stage(float2* buf, const float2* M, int tid) {
    const int m = 1 << B;
    const int low = tid & (m - 1);
    const int base = ((tid >> B) << (B + 2)) | low;
    float2 a0 = buf[base];
    float2 a1 = buf[base + m];
    float2 a2 = buf[base + 2 * m];
    float2 a3 = buf[base + 3 * m];
    float2 o0 = make_float2(0.f, 0.f), o1 = o0, o2 = o0, o3 = o0;
    o0 = cmac(M[0],  a0, o0); o0 = cmac(M[1],  a1, o0); o0 = cmac(M[2],  a2, o0); o0 = cmac(M[3],  a3, o0);
    o1 = cmac(M[4],  a0, o1); o1 = cmac(M[5],  a1, o1); o1 = cmac(M[6],  a2, o1); o1 = cmac(M[7],  a3, o1);
    o2 = cmac(M[8],  a0, o2); o2 = cmac(M[9],  a1, o2); o2 = cmac(M[10], a2, o2); o2 = cmac(M[11], a3, o2);
    o3 = cmac(M[12], a0, o3); o3 = cmac(M[13], a1, o3); o3 = cmac(M[14], a2, o3); o3 = cmac(M[15], a3, o3);
    buf[base]         = o0;
    buf[base + m]     = o1;
    buf[base + 2 * m] = o2;
    buf[base + 3 * m] = o3;
    __syncthreads();
}

__global__ __launch_bounds__(SIM_THREADS, 1)
void qae_sim_kernel(const float* __restrict__ w,     // (3,12,3)
                    const float* __restrict__ W1,    // (32,12)
                    const float* __restrict__ b1,    // (32,)
                    const float* __restrict__ W2,    // (16,32)
                    const float* __restrict__ b2)    // (16,)
{
    __shared__ float2 buf[4096];            // 32 KB statevector
    __shared__ float2 sG[36][4];            // per (layer,qubit) fused RZ@RY@RX
    __shared__ float2 sM4[12][16];          // fused 4x4 two-qubit stage matrices (layers 2,3)
    __shared__ unsigned short gtab[4096];   // CNOT-ring gather map (P^-1)
    __shared__ float2 sHi[64], sLo[64];     // layer-1 product-state prefix tables
    __shared__ int   smask[12];             // forward-perm parity masks (P3 fold)
    __shared__ float sPart[32][12];
    __shared__ float sZ[12], sH[32];

    const int tid = threadIdx.x;

    // ---- per-(layer,qubit) 2x2 gates: M = RZ @ RY @ RX ----
    if (tid < 36) {
        const float* wp = w + tid * 3;
        float hx = 0.5f * wp[0], hy = 0.5f * wp[1], hz = 0.5f * wp[2];
        float cx, sx, cy, sy, cz, sz;
        sincosf(hx, &sx, &cx);
        sincosf(hy, &sy, &cy);
        sincosf(hz, &sz, &cz);
        float2 RX00 = make_float2(cx, 0.f), RX01 = make_float2(0.f, -sx);
        float2 RX10 = make_float2(0.f, -sx), RX11 = make_float2(cx, 0.f);
        float2 RY00 = make_float2(cy, 0.f), RY01 = make_float2(-sy, 0.f);
        float2 RY10 = make_float2(sy, 0.f), RY11 = make_float2(cy, 0.f);
        float2 RZ0 = make_float2(cz, -sz), RZ1 = make_float2(cz, sz);
        float2 A00 = make_float2(cmul(RY00, RX00).x + cmul(RY01, RX10).x,
                                 cmul(RY00, RX00).y + cmul(RY01, RX10).y);
        float2 A01 = make_float2(cmul(RY00, RX01).x + cmul(RY01, RX11).x,
                                 cmul(RY00, RX01).y + cmul(RY01, RX11).y);
        float2 A10 = make_float2(cmul(RY10, RX00).x + cmul(RY11, RX10).x,
                                 cmul(RY10, RX00).y + cmul(RY11, RX10).y);
        float2 A11 = make_float2(cmul(RY10, RX01).x + cmul(RY11, RX11).x,
                                 cmul(RY10, RX01).y + cmul(RY11, RX11).y);
        sG[tid][0] = cmul(RZ0, A00);
        sG[tid][1] = cmul(RZ0, A01);
        sG[tid][2] = cmul(RZ1, A10);
        sG[tid][3] = cmul(RZ1, A11);
    }

    // ---- CNOT-ring gather map g = P^-1 (new[i] = old[g(i)]) ----
    #pragma unroll
    for (int k = 0; k < 4; k++) {
        int i = tid * 4 + k;
        int j = i;
        #pragma unroll
        for (int q = 11; q >= 0; q--) {
            int c = 11 - q;
            int t = 11 - ((q + 1) % 12);
            if ((j >> c) & 1) j ^= (1 << t);
        }
        gtab[i] = (unsigned short)j;
    }

    // ---- forward-perm parity masks: bit_b(P(j)) = parity(j & smask[b]) ----
    if (tid == 0) {
        int m[12];
        #pragma unroll
        for (int k = 0; k < 12; k++) m[k] = 1 << k;
        #pragma unroll
        for (int q = 0; q < 12; q++) {
            int c = 11 - q;
            int t = 11 - ((q + 1) % 12);
            m[t] ^= m[c];
        }
        #pragma unroll
        for (int k = 0; k < 12; k++) smask[k] = m[k];
    }
    __syncthreads();

    // ---- fused 4x4 stage matrices for layers 2,3 ----
    // stage s (0..11): layer = 1 + s/6, bit pair (2b, 2b+1), b = s%6
    // bits 2b <-> qubit 11-2b (lo), 2b+1 <-> qubit 10-2b (hi)
    if (tid < 192) {
        int s = tid >> 4, e = tid & 15;
        int l = 1 + s / 6, b = s % 6;
        int qlo = 11 - 2 * b, qhi = 10 - 2 * b;
        int eo = e >> 2, ei = e & 3;
        float2 mh = sG[l * 12 + qhi][(eo >> 1) * 2 + (ei >> 1)];
        float2 ml = sG[l * 12 + qlo][(eo & 1) * 2 + (ei & 1)];
        sM4[s][e] = cmul(mh, ml);
    }
    // ---- layer-1 product state prefix tables ----
    if (tid < 64) {                       // hi: qubits 0..5 <-> index bits 11..6
        int h = tid;
        float2 p = make_float2(1.f, 0.f);
        #pragma unroll
        for (int q = 0; q < 6; q++) {
            int bit = (h >> (5 - q)) & 1;
            p = cmul(p, bit ? sG[q][2] : sG[q][0]);   // column 0 of gate: (M00, M10)
        }
        sHi[h] = p;
    } else if (tid < 128) {               // lo: qubits 6..11 <-> index bits 5..0
        int mI = tid - 64;
        float2 p = make_float2(1.f, 0.f);
        #pragma unroll
        for (int q = 6; q < 12; q++) {
            int bit = (mI >> (11 - q)) & 1;
            p = cmul(p, bit ? sG[q][2] : sG[q][0]);
        }
        sLo[mI] = p;
    }
    __syncthreads();

    // ================= layer 2: stage 0 with P1-folded product gather =======
    {
        const int base = tid * 4;
        float2 in[4];
        #pragma unroll
        for (int k = 0; k < 4; k++) {
            int gi = gtab[base + k];
            in[k] = cmul(sHi[gi >> 6], sLo[gi & 63]);
        }
        const float2* M = sM4[0];
        #pragma unroll
        for (int e = 0; e < 4; e++) {
            float2 o = make_float2(0.f, 0.f);
            #pragma unroll
            for (int e2 = 0; e2 < 4; e2++) o = cmac(M[e * 4 + e2], in[e2], o);
            buf[base + e] = o;
        }
        __syncthreads();
    }
    apply_stage<2>(buf,  sM4[1], tid);
    apply_stage<4>(buf,  sM4[2], tid);
    apply_stage<6>(buf,  sM4[3], tid);
    apply_stage<8>(buf,  sM4[4], tid);
    apply_stage<10>(buf, sM4[5], tid);

    // ================= layer 3: stage 0 with P2-folded gather ===============
    {
        const int base = tid * 4;
        float2 in[4];
        #pragma unroll
        for (int k = 0; k < 4; k++) in[k] = buf[gtab[base + k]];
        __syncthreads();                       // all reads done before writes
        const float2* M = sM4[6];
        #pragma unroll
        for (int e = 0; e < 4; e++) {
            float2 o = make_float2(0.f, 0.f);
            #pragma unroll
            for (int e2 = 0; e2 < 4; e2++) o = cmac(M[e * 4 + e2], in[e2], o);
            buf[base + e] = o;
        }
        __syncthreads();
    }
    apply_stage<2>(buf,  sM4[7], tid);
    apply_stage<4>(buf,  sM4[8], tid);
    apply_stage<6>(buf,  sM4[9], tid);
    apply_stage<8>(buf,  sM4[10], tid);
    apply_stage<10>(buf, sM4[11], tid);

    // ========== <Z_q> reduction with P3 folded as parity sign masks =========
    float zloc[12];
    #pragma unroll
    for (int q = 0; q < 12; q++) zloc[q] = 0.f;
    #pragma unroll
    for (int k = 0; k < 4; k++) {
        int i = tid * 4 + k;
        float2 a = buf[i];
        float pr = a.x * a.x + a.y * a.y;
        #pragma unroll
        for (int q = 0; q < 12; q++)
            zloc[q] += (__popc(i & smask[11 - q]) & 1) ? -pr : pr;
    }
    #pragma unroll
    for (int q = 0; q < 12; q++) {
        float x = zloc[q];
        #pragma unroll
        for (int off = 16; off > 0; off >>= 1)
            x += __shfl_down_sync(0xFFFFFFFFu, x, off);
        zloc[q] = x;
    }
    int warp = tid >> 5, lane = tid & 31;
    if (lane == 0) {
        #pragma unroll
        for (int q = 0; q < 12; q++) sPart[warp][q] = zloc[q];
    }
    __syncthreads();
    if (tid < 12) {
        float s = 0.f;
        #pragma unroll
        for (int wi = 0; wi < 32; wi++) s += sPart[wi][tid];
        sZ[tid] = s;
    }
    __syncthreads();

    // ---- MLP head ----
    if (tid < 32) {
        float acc = b1[tid];
        #pragma unroll
        for (int k = 0; k < 12; k++) acc += W1[tid * 12 + k] * sZ[k];
        sH[tid] = fmaxf(acc, 0.f);
    }
    __syncthreads();
    if (tid < 16) {
        float acc = b2[tid];
        #pragma unroll
        for (int k = 0; k < 32; k++) acc += W2[tid * 32 + k] * sH[k];
        g_pix[tid] = 1.f / (1.f + expf(-acc));
    }
}

// Broadcast 64B pattern across the 64 MiB output: 4 independent STG.128/thread.
__global__ __launch_bounds__(256)
void qae_bcast_kernel(float4* __restrict__ out, int n4)
{
    int idx = blockIdx.x * 256 + threadIdx.x;
    int total = gridDim.x * 256;                     // multiple of 4
    float4 v = reinterpret_cast<const float4*>(g_pix)[idx & 3];
    int i0 = idx, i1 = idx + total, i2 = idx + 2 * total, i3 = idx + 3 * total;
    if (i3 < n4) {                                   // fast path: all 4 in range
        out[i0] = v; out[i1] = v; out[i2] = v; out[i3] = v;
        for (int i = idx + 4 * total; i < n4; i += total) out[i] = v;
    } else {
        for (int i = i0; i < n4; i += total) out[i] = v;
    }
}

extern "C" void kernel_launch(void* const* d_in, const int* in_sizes, int n_in,
                              void* d_out, int out_size)
{
    // metadata order: images, qweights, W1, b1, W2, b2
    const float* w  = (const float*)d_in[1];
    const float* W1 = (const float*)d_in[2];
    const float* b1 = (const float*)d_in[3];
    const float* W2 = (const float*)d_in[4];
    const float* b2 = (const float*)d_in[5];

    qae_sim_kernel<<<1, SIM_THREADS>>>(w, W1, b1, W2, b2);

    int n4 = out_size / 4;                           // float4 count
    int threads = 256;
    int blocks = (n4 + threads * 4 - 1) / (threads * 4);   // exactly 4 stores/thread
    if (blocks < 1) blocks = 1;
    qae_bcast_kernel<<<blocks, threads>>>((float4*)d_out, n4);
}

// round 4
// speedup vs baseline: 1.1294x; 1.0066x over previous
#include <cuda_runtime.h>
#include <math.h>

#define SIM_THREADS 1024

__device__ float g_pix[16];   // 16 sigmoid pixels (final pattern)

// phys layout: pad 4 float2 slots per 16 -> conflict-free strided stage access
__device__ __forceinline__ int SW_PHYS(int i) { return i + ((i >> 4) << 2); }

__device__ __forceinline__ float2 cmul(float2 a, float2 b) {
    return make_float2(a.x * b.x - a.y * b.y, a.x * b.y + a.y * b.x);
}

// ---- packed f32x2 helpers ----
__device__ __forceinline__ unsigned long long pack2(float x, float y) {
    unsigned long long r;
    asm("mov.b64 %0, {%1, %2};" : "=l"(r) : "f"(x), "f"(y));
    return r;
}
__device__ __forceinline__ float2 unpack2(unsigned long long v) {
    float2 r;
    asm("mov.b64 {%0, %1}, %2;" : "=f"(r.x), "=f"(r.y) : "l"(v));
    return r;
}
__device__ __forceinline__ unsigned long long ffma2(unsigned long long a,
                                                    unsigned long long b,
                                                    unsigned long long c) {
    unsigned long long d;
    asm("fma.rn.f32x2 %0, %1, %2, %3;" : "=l"(d) : "l"(a), "l"(b), "l"(c));
    return d;
}
__device__ __forceinline__ unsigned long long fmul2(unsigned long long a,
                                                    unsigned long long b) {
    unsigned long long d;
    asm("mul.rn.f32x2 %0, %1, %2;" : "=l"(d) : "l"(a), "l"(b));
    return d;
}

// 4x4 complex mat-vec in packed form. M4[e*4+e2] = {mx, mx, -my, my}.
// in: a[k] packed (re,im), s[k] packed (im,re). out written to outv[].
__device__ __forceinline__ void mat4_apply(const float4* __restrict__ M4,
                                           const unsigned long long* a,
                                           const unsigned long long* s,
                                           unsigned long long* outv) {
    #pragma unroll
    for (int e = 0; e < 4; e++) {
        float4 q0 = M4[e * 4 + 0];
        float4 q1 = M4[e * 4 + 1];
        float4 q2 = M4[e * 4 + 2];
        float4 q3 = M4[e * 4 + 3];
        const unsigned long long* p0 = reinterpret_cast<const unsigned long long*>(&q0);
        const unsigned long long* p1 = reinterpret_cast<const unsigned long long*>(&q1);
        const unsigned long long* p2 = reinterpret_cast<const unsigned long long*>(&q2);
        const unsigned long long* p3 = reinterpret_cast<const unsigned long long*>(&q3);
        unsigned long long o = fmul2(p0[0], a[0]);
        o = ffma2(p0[1], s[0], o);
        o = ffma2(p1[0], a[1], o);
        o = ffma2(p1[1], s[1], o);
        o = ffma2(p2[0], a[2], o);
        o = ffma2(p2[1], s[2], o);
        o = ffma2(p3[0], a[3], o);
        o = ffma2(p3[1], s[3], o);
        outv[e] = o;
    }
}

// In-place 4x4 stage on bits (B, B+1); thread owns one quad; padded layout.
template<int B>
__device__ __forceinline__ void apply_stage(float2* buf, const float4* M4, int tid) {
    const int m = 1 << B;
    const int stride = (B >= 4) ? (m + (m >> 2)) : m;   // phys stride of quad
    const int low = tid & (m - 1);
    const int base = ((tid >> B) << (B + 2)) | low;
    const int pb = SW_PHYS(base);
    unsigned long long a[4], s[4], o[4];
    #pragma unroll
    for (int k = 0; k < 4; k++) {
        float2 v = buf[pb + k * stride];
        a[k] = pack2(v.x, v.y);
        s[k] = pack2(v.y, v.x);
    }
    mat4_apply(M4, a, s, o);
    #pragma unroll
    for (int k = 0; k < 4; k++)
        buf[pb + k * stride] = unpack2(o[k]);
    __syncthreads();
}

__global__ __launch_bounds__(SIM_THREADS, 1)
void qae_sim_kernel(const float* __restrict__ w,     // (3,12,3)
                    const float* __restrict__ W1,    // (32,12)
                    const float* __restrict__ b1,    // (32,)
                    const float* __restrict__ W2,    // (16,32)
                    const float* __restrict__ b2)    // (16,)
{
    __shared__ float2 buf[5120];            // 4096 amps padded (40 KB)
    __shared__ float4 sM4[12][16];          // packed {mx,mx,-my,my} stage mats
    __shared__ float2 sG[36][4];            // per (layer,qubit) RZ@RY@RX
    __shared__ float2 sHi[64], sLo[64];     // layer-1 product prefix tables
    __shared__ int    sBinv[12];            // basis of inverse CNOT-ring perm
    __shared__ int    smask[12];            // forward-perm parity masks
    __shared__ float  sPart[32][12];
    __shared__ float  sZ[12], sH[32];

    const int tid = threadIdx.x;

    // ---- per-(layer,qubit) 2x2 gates: M = RZ @ RY @ RX ----
    if (tid < 36) {
        const float* wp = w + tid * 3;
        float hx = 0.5f * wp[0], hy = 0.5f * wp[1], hz = 0.5f * wp[2];
        float cx, sx, cy, sy, cz, sz;
        sincosf(hx, &sx, &cx);
        sincosf(hy, &sy, &cy);
        sincosf(hz, &sz, &cz);
        float2 RX00 = make_float2(cx, 0.f), RX01 = make_float2(0.f, -sx);
        float2 RX10 = make_float2(0.f, -sx), RX11 = make_float2(cx, 0.f);
        float2 RY00 = make_float2(cy, 0.f), RY01 = make_float2(-sy, 0.f);
        float2 RY10 = make_float2(sy, 0.f), RY11 = make_float2(cy, 0.f);
        float2 RZ0 = make_float2(cz, -sz), RZ1 = make_float2(cz, sz);
        float2 t00 = cmul(RY00, RX00), t00b = cmul(RY01, RX10);
        float2 t01 = cmul(RY00, RX01), t01b = cmul(RY01, RX11);
        float2 t10 = cmul(RY10, RX00), t10b = cmul(RY11, RX10);
        float2 t11 = cmul(RY10, RX01), t11b = cmul(RY11, RX11);
        float2 A00 = make_float2(t00.x + t00b.x, t00.y + t00b.y);
        float2 A01 = make_float2(t01.x + t01b.x, t01.y + t01b.y);
        float2 A10 = make_float2(t10.x + t10b.x, t10.y + t10b.y);
        float2 A11 = make_float2(t11.x + t11b.x, t11.y + t11b.y);
        sG[tid][0] = cmul(RZ0, A00);
        sG[tid][1] = cmul(RZ0, A01);
        sG[tid][2] = cmul(RZ1, A10);
        sG[tid][3] = cmul(RZ1, A11);
    }

    // ---- basis of inverse CNOT-ring permutation (linear over GF(2)) ----
    if (tid >= 64 && tid < 76) {
        int b = tid - 64;
        int j = 1 << b;
        #pragma unroll
        for (int q = 11; q >= 0; q--) {
            int c = 11 - q;
            int t = 11 - ((q + 1) % 12);
            if ((j >> c) & 1) j ^= (1 << t);
        }
        sBinv[b] = j;
    }
    // ---- forward-perm parity masks: bit_b(P(j)) = parity(j & smask[b]) ----
    if (tid == 128) {
        int m[12];
        #pragma unroll
        for (int k = 0; k < 12; k++) m[k] = 1 << k;
        #pragma unroll
        for (int q = 0; q < 12; q++) {
            int c = 11 - q;
            int t = 11 - ((q + 1) % 12);
            m[t] ^= m[c];
        }
        #pragma unroll
        for (int k = 0; k < 12; k++) smask[k] = m[k];
    }
    __syncthreads();

    // ---- register-resident gather indices g(4t+k) via linearity ----
    int gr[4];
    {
        int idx4 = tid << 2;
        int gb = 0;
        #pragma unroll
        for (int b = 2; b < 12; b++)
            if ((idx4 >> b) & 1) gb ^= sBinv[b];
        gr[0] = gb;
        gr[1] = gb ^ sBinv[0];
        gr[2] = gb ^ sBinv[1];
        gr[3] = gb ^ sBinv[1] ^ sBinv[0];
    }

    // ---- packed 4x4 stage matrices for layers 2,3 ----
    // stage s: layer 1 + s/6, bit pair (2b,2b+1), b=s%6; bit p <-> qubit 11-p
    if (tid < 192) {
        int s = tid >> 4, e = tid & 15;
        int l = 1 + s / 6, b = s % 6;
        int qlo = 11 - 2 * b, qhi = 10 - 2 * b;
        int eo = e >> 2, ei = e & 3;
        float2 mh = sG[l * 12 + qhi][(eo >> 1) * 2 + (ei >> 1)];
        float2 ml = sG[l * 12 + qlo][(eo & 1) * 2 + (ei & 1)];
        float2 mm = cmul(mh, ml);
        sM4[s][e] = make_float4(mm.x, mm.x, -mm.y, mm.y);
    }
    // ---- layer-1 product-state prefix tables ----
    if (tid >= 256 && tid < 320) {        // hi: qubits 0..5 <-> bits 11..6
        int h = tid - 256;
        float2 p = make_float2(1.f, 0.f);
        #pragma unroll
        for (int q = 0; q < 6; q++) {
            int bit = (h >> (5 - q)) & 1;
            p = cmul(p, bit ? sG[q][2] : sG[q][0]);
        }
        sHi[h] = p;
    } else if (tid >= 320 && tid < 384) { // lo: qubits 6..11 <-> bits 5..0
        int mI = tid - 320;
        float2 p = make_float2(1.f, 0.f);
        #pragma unroll
        for (int q = 6; q < 12; q++) {
            int bit = (mI >> (11 - q)) & 1;
            p = cmul(p, bit ? sG[q][2] : sG[q][0]);
        }
        sLo[mI] = p;
    }
    __syncthreads();

    // ===== layer 2, stage (0,1) with P1-folded product gather =====
    {
        const int pb = SW_PHYS(tid << 2);
        unsigned long long a[4], s[4], o[4];
        #pragma unroll
        for (int k = 0; k < 4; k++) {
            float2 v = cmul(sHi[gr[k] >> 6], sLo[gr[k] & 63]);
            a[k] = pack2(v.x, v.y);
            s[k] = pack2(v.y, v.x);
        }
        mat4_apply(sM4[0], a, s, o);
        #pragma unroll
        for (int e = 0; e < 4; e++) buf[pb + e] = unpack2(o[e]);
        __syncthreads();
    }
    apply_stage<2>(buf,  sM4[1], tid);
    apply_stage<4>(buf,  sM4[2], tid);
    apply_stage<6>(buf,  sM4[3], tid);
    apply_stage<8>(buf,  sM4[4], tid);
    apply_stage<10>(buf, sM4[5], tid);

    // ===== layer 3, stage (0,1) with P2-folded gather =====
    {
        const int pb = SW_PHYS(tid << 2);
        unsigned long long a[4], s[4], o[4];
        #pragma unroll
        for (int k = 0; k < 4; k++) {
            float2 v = buf[SW_PHYS(gr[k])];
            a[k] = pack2(v.x, v.y);
            s[k] = pack2(v.y, v.x);
        }
        __syncthreads();                  // all reads done before overwrites
        mat4_apply(sM4[6], a, s, o);
        #pragma unroll
        for (int e = 0; e < 4; e++) buf[pb + e] = unpack2(o[e]);
        __syncthreads();
    }
    apply_stage<2>(buf,  sM4[7], tid);
    apply_stage<4>(buf,  sM4[8], tid);
    apply_stage<6>(buf,  sM4[9], tid);
    apply_stage<8>(buf,  sM4[10], tid);
    apply_stage<10>(buf, sM4[11], tid);

    // ===== <Z_q> reduction, P3 folded as parity sign masks =====
    float zloc[12];
    #pragma unroll
    for (int q = 0; q < 12; q++) zloc[q] = 0.f;
    {
        const int pb = SW_PHYS(tid << 2);
        #pragma unroll
        for (int k = 0; k < 4; k++) {
            int i = (tid << 2) + k;
            float2 aa = buf[pb + k];
            float pr = aa.x * aa.x + aa.y * aa.y;
            #pragma unroll
            for (int q = 0; q < 12; q++)
                zloc[q] += (__popc(i & smask[11 - q]) & 1) ? -pr : pr;
        }
    }
    #pragma unroll
    for (int q = 0; q < 12; q++) {
        float x = zloc[q];
        #pragma unroll
        for (int off = 16; off > 0; off >>= 1)
            x += __shfl_down_sync(0xFFFFFFFFu, x, off);
        zloc[q] = x;
    }
    int warp = tid >> 5, lane = tid & 31;
    if (lane == 0) {
        #pragma unroll
        for (int q = 0; q < 12; q++) sPart[warp][q] = zloc[q];
    }
    __syncthreads();
    if (tid < 12) {
        float s = 0.f;
        #pragma unroll
        for (int wi = 0; wi < 32; wi++) s += sPart[wi][tid];
        sZ[tid] = s;
    }
    __syncthreads();

    // ---- MLP head: 12 -> 32 (ReLU) -> 16 (sigmoid) ----
    if (tid < 32) {
        float acc = b1[tid];
        #pragma unroll
        for (int k = 0; k < 12; k++) acc += W1[tid * 12 + k] * sZ[k];
        sH[tid] = fmaxf(acc, 0.f);
    }
    __syncthreads();
    if (tid < 16) {
        float acc = b2[tid];
        #pragma unroll
        for (int k = 0; k < 32; k++) acc += W2[tid * 32 + k] * sH[k];
        g_pix[tid] = 1.f / (1.f + expf(-acc));
    }
}

// Broadcast 64B pattern across the 64 MiB output: 8 unrolled STG.128/thread.
__global__ __launch_bounds__(256)
void qae_bcast_kernel(float4* __restrict__ out, int n4)
{
    int t = blockIdx.x * 256 + threadIdx.x;
    int total = gridDim.x * 256;                    // multiple of 4
    float4 v = reinterpret_cast<const float4*>(g_pix)[t & 3];
    int i = t;
    if (t + 7 * total < n4) {
        #pragma unroll
        for (int k = 0; k < 8; k++) out[t + k * total] = v;
        i = t + 8 * total;
    }
    for (; i < n4; i += total) out[i] = v;
}

extern "C" void kernel_launch(void* const* d_in, const int* in_sizes, int n_in,
                              void* d_out, int out_size)
{
    // metadata order: images, qweights, W1, b1, W2, b2
    const float* w  = (const float*)d_in[1];
    const float* W1 = (const float*)d_in[2];
    const float* b1 = (const float*)d_in[3];
    const float* W2 = (const float*)d_in[4];
    const float* b2 = (const float*)d_in[5];

    qae_sim_kernel<<<1, SIM_THREADS>>>(w, W1, b1, W2, b2);

    int n4 = out_size / 4;                           // float4 count
    int blocks = n4 / (256 * 8);                     // exact for B=1M
    if (blocks < 1) blocks = 1;
    qae_bcast_kernel<<<blocks, 256>>>((float4*)d_out, n4);
}